// round 3
// baseline (speedup 1.0000x reference)
#include <cuda_runtime.h>
#include <math.h>

#define NEXP    8
#define NPAIR   4                // expert pairs
#define HDIM    4096
#define TOK     4
#define WARPS   16
#define THREADS 512
#define NTOK    16384            // 4 * 4096 tokens
#define NGROUP  (NTOK / TOK)     // 4096 warp-groups
#define H4      (HDIM / 4)       // 1024 float4 per row
#define KITERS  (H4 / 32)        // 32 k-iterations per group

// ---- packed f32x2 helpers (Blackwell FFMA2 — PTX-only pattern) ----
__device__ __forceinline__ unsigned long long dup2(float a) {
    unsigned long long r;
    asm("mov.b64 %0, {%1, %1};" : "=l"(r) : "f"(a));
    return r;
}
__device__ __forceinline__ void fma2(unsigned long long& d,
                                     unsigned long long a,
                                     unsigned long long b) {
    asm("fma.rn.f32x2 %0, %1, %2, %0;" : "+l"(d) : "l"(a), "l"(b));
}
__device__ __forceinline__ unsigned long long add2(unsigned long long a,
                                                   unsigned long long b) {
    unsigned long long r;
    asm("add.rn.f32x2 %0, %1, %2;" : "=l"(r) : "l"(a), "l"(b));
    return r;
}
__device__ __forceinline__ void unpack2(unsigned long long v, float& lo, float& hi) {
    asm("mov.b64 {%0, %1}, %2;" : "=f"(lo), "=f"(hi) : "l"(v));
}

__global__ __launch_bounds__(THREADS, 1)
void moe_router_kernel(const float* __restrict__ hs,
                       const float* __restrict__ rw,
                       float* __restrict__ out)
{
    // Packed weight layout, 128 KB total:
    // per (pair p, iter i): 256 floats =
    //   plane A [lane][4] = {e0@k0, e1@k0, e0@k1, e1@k1}   (k0 = (i*32+lane)*4)
    //   plane B [lane][4] = {e0@k2, e1@k2, e0@k3, e1@k3}
    // Lane LDS.128 stride = 16B -> conflict-free; each float4 = 2 f32x2 operands.
    extern __shared__ float sw[];

    // Stage + interleave router weights (coalesced reads, scattered smem writes; once)
    {
        const float4* rw4 = reinterpret_cast<const float4*>(rw);
        for (int idx = threadIdx.x; idx < NEXP * H4; idx += THREADS) {
            const int e  = idx >> 10;          // expert
            const int k4 = idx & 1023;         // float4 index along H
            const float4 v = rw4[(size_t)e * H4 + k4];
            const int p   = e >> 1;
            const int par = e & 1;
            const int l   = k4 & 31;
            const int i   = k4 >> 5;
            // base of (p,i) block in floats
            const int base = (p * KITERS + i) * 256;
            // r = 0..3 within the lane's float4 of hidden
            sw[base +   0 + l * 4 + 0 * 2 + par] = v.x;  // r=0 -> plane A
            sw[base +   0 + l * 4 + 1 * 2 + par] = v.y;  // r=1 -> plane A
            sw[base + 128 + l * 4 + 0 * 2 + par] = v.z;  // r=2 -> plane B
            sw[base + 128 + l * 4 + 1 * 2 + par] = v.w;  // r=3 -> plane B
        }
    }
    __syncthreads();

    const int lane = threadIdx.x & 31;
    const int wid  = threadIdx.x >> 5;
    // Interleaved warp indexing: spreads multi-group warps across all SMs
    const int gwarp = wid * gridDim.x + blockIdx.x;
    const int nwarp = gridDim.x * WARPS;

    const ulonglong2* swu = reinterpret_cast<const ulonglong2*>(sw);

    float* out_w = out;                     // [NTOK, 2] top-k weights
    float* out_i = out + (size_t)NTOK * 2;  // [NTOK, 2] indices (as float)
    float* out_l = out + (size_t)NTOK * 4;  // [NTOK, 8] raw logits

    for (int g = gwarp; g < NGROUP; g += nwarp) {
        const size_t t0 = (size_t)g * TOK;
        const float4* hs4 = reinterpret_cast<const float4*>(hs) + t0 * H4;

        unsigned long long acc[TOK][NPAIR];   // {logit[2p], logit[2p+1]}
        #pragma unroll
        for (int t = 0; t < TOK; t++)
            #pragma unroll
            for (int p = 0; p < NPAIR; p++)
                acc[t][p] = 0ull;

        // Double-buffered hidden loads
        float4 hbuf[2][TOK];
        #pragma unroll
        for (int t = 0; t < TOK; t++)
            hbuf[0][t] = __ldcs(&hs4[(size_t)t * H4 + lane]);

        #pragma unroll 4
        for (int i = 0; i < KITERS; i++) {
            const int cur = i & 1;

            if (i + 1 < KITERS) {
                const int kk2 = (i + 1) * 32 + lane;
                #pragma unroll
                for (int t = 0; t < TOK; t++)
                    hbuf[cur ^ 1][t] = __ldcs(&hs4[(size_t)t * H4 + kk2]);
            }

            // Packed weights: per pair, plane A and plane B (each = 2 f32x2)
            ulonglong2 wa[NPAIR], wb[NPAIR];
            #pragma unroll
            for (int p = 0; p < NPAIR; p++) {
                const int u2base = (p * KITERS + i) * 64 + lane;  // in 16B units
                wa[p] = swu[u2base];
                wb[p] = swu[u2base + 32];
            }

            #pragma unroll
            for (int t = 0; t < TOK; t++) {
                const float4 h = hbuf[cur][t];
                const unsigned long long hx = dup2(h.x);
                const unsigned long long hy = dup2(h.y);
                const unsigned long long hz = dup2(h.z);
                const unsigned long long hw = dup2(h.w);
                #pragma unroll
                for (int p = 0; p < NPAIR; p++) {
                    fma2(acc[t][p], hx, wa[p].x);
                    fma2(acc[t][p], hy, wa[p].y);
                    fma2(acc[t][p], hz, wb[p].x);
                    fma2(acc[t][p], hw, wb[p].y);
                }
            }
        }

        // Butterfly reduction on packed pairs
        #pragma unroll
        for (int off = 16; off > 0; off >>= 1) {
            #pragma unroll
            for (int t = 0; t < TOK; t++)
                #pragma unroll
                for (int p = 0; p < NPAIR; p++) {
                    const unsigned long long o =
                        __shfl_xor_sync(0xffffffffu, acc[t][p], off);
                    acc[t][p] = add2(acc[t][p], o);
                }
        }

        // Lanes 0..TOK-1: one token each — top-2 + renorm + writes
        if (lane < TOK) {
            float l[NEXP];
            #pragma unroll
            for (int t = 0; t < TOK; t++) {
                if (lane == t) {
                    #pragma unroll
                    for (int p = 0; p < NPAIR; p++)
                        unpack2(acc[t][p], l[2 * p], l[2 * p + 1]);
                }
            }

            const size_t tok = t0 + lane;

            // argmax (ties -> lowest index, matching jax.lax.top_k)
            int   i1 = 0; float v1 = l[0];
            #pragma unroll
            for (int e = 1; e < NEXP; e++)
                if (l[e] > v1) { v1 = l[e]; i1 = e; }
            int   i2 = -1; float v2 = -INFINITY;
            #pragma unroll
            for (int e = 0; e < NEXP; e++)
                if (e != i1 && l[e] > v2) { v2 = l[e]; i2 = e; }

            // renormalized top-2 softmax weights
            const float e2 = __expf(v2 - v1);
            const float r  = 1.0f / (1.0f + e2);

            out_w[tok * 2 + 0] = r;
            out_w[tok * 2 + 1] = e2 * r;
            out_i[tok * 2 + 0] = (float)i1;
            out_i[tok * 2 + 1] = (float)i2;
            #pragma unroll
            for (int e = 0; e < NEXP; e++)
                out_l[tok * NEXP + e] = l[e];
        }
    }
}

extern "C" void kernel_launch(void* const* d_in, const int* in_sizes, int n_in,
                              void* d_out, int out_size)
{
    const float* hs = (const float*)d_in[0];   // hidden_states [4,4096,4096] f32
    const float* rw = (const float*)d_in[1];   // router_weight [8,4096] f32
    float* out = (float*)d_out;

    (void)in_sizes; (void)n_in; (void)out_size;

    cudaFuncSetAttribute(moe_router_kernel,
                         cudaFuncAttributeMaxDynamicSharedMemorySize,
                         NEXP * HDIM * (int)sizeof(float));

    moe_router_kernel<<<152, THREADS, NEXP * HDIM * sizeof(float)>>>(hs, rw, out);
}